// round 1
// baseline (speedup 1.0000x reference)
#include <cuda_runtime.h>
#include <stdint.h>
#include <math.h>

#define NTOK 16384
#define HD   4096
#define NE   64
#define NP   6
#define TK   8

#define WARPS    16
#define TPW      4                 // tokens per warp
#define TPB      (WARPS * TPW)     // 64 tokens per block
#define NTHREADS (WARPS * 32)
#define H4       (HD / 4)          // 1024 float4 per row
#define HU       (HD / 4)          // ulonglong2 units per comp row (16B each) = 1024

// smem: comp[NP*HD] | cent[NE*NP] | centn[NE] | proj[TPB*NP] | cpart[WARPS*NP] | cvec[NP]
#define SMEM_FLOATS (NP*HD + NE*NP + NE + TPB*NP + WARPS*NP + NP)
#define SMEM_BYTES  (SMEM_FLOATS * 4)

#define FMA2(acc, a, b) \
    asm("fma.rn.f32x2 %0, %1, %2, %0;" : "+l"(acc) : "l"(a), "l"(b))

__global__ void __launch_bounds__(NTHREADS, 1)
kdtree_router_kernel(const float* __restrict__ x,
                     const float* __restrict__ mean,
                     const float* __restrict__ comp,
                     const float* __restrict__ cent,
                     float* __restrict__ out)
{
    extern __shared__ float smem[];
    float* comp_s  = smem;                       // NP*HD
    float* cent_s  = comp_s + NP * HD;           // NE*NP
    float* centn_s = cent_s + NE * NP;           // NE
    float* proj_s  = centn_s + NE;               // TPB*NP
    float* cpart   = proj_s + TPB * NP;          // WARPS*NP
    float* cvec    = cpart + WARPS * NP;         // NP

    const int tid  = threadIdx.x;
    const int lane = tid & 31;
    const int warp = tid >> 5;

    // ---- load PCA components + centroids into smem ----
    {
        const float4* cg = (const float4*)comp;
        float4* cs = (float4*)comp_s;
        #pragma unroll
        for (int i = tid; i < NP * H4; i += NTHREADS) cs[i] = cg[i];
        for (int i = tid; i < NE * NP; i += NTHREADS) cent_s[i] = cent[i];
    }
    __syncthreads();

    // ---- per-block constant: cvec[p] = sum_h mean[h]*comp[p][h]; centroid norms ----
    {
        float a0=0.f,a1=0.f,a2=0.f,a3=0.f,a4=0.f,a5=0.f;
        #pragma unroll
        for (int j = 0; j < 8; j++) {
            int h = warp * 256 + lane + j * 32;
            float m = __ldg(mean + h);
            a0 += m * comp_s[0*HD + h];
            a1 += m * comp_s[1*HD + h];
            a2 += m * comp_s[2*HD + h];
            a3 += m * comp_s[3*HD + h];
            a4 += m * comp_s[4*HD + h];
            a5 += m * comp_s[5*HD + h];
        }
        #pragma unroll
        for (int o = 16; o > 0; o >>= 1) {
            a0 += __shfl_xor_sync(0xffffffffu, a0, o);
            a1 += __shfl_xor_sync(0xffffffffu, a1, o);
            a2 += __shfl_xor_sync(0xffffffffu, a2, o);
            a3 += __shfl_xor_sync(0xffffffffu, a3, o);
            a4 += __shfl_xor_sync(0xffffffffu, a4, o);
            a5 += __shfl_xor_sync(0xffffffffu, a5, o);
        }
        if (lane == 0) {
            cpart[warp*NP+0]=a0; cpart[warp*NP+1]=a1; cpart[warp*NP+2]=a2;
            cpart[warp*NP+3]=a3; cpart[warp*NP+4]=a4; cpart[warp*NP+5]=a5;
        }
        if (tid < NE) {
            float s = 0.f;
            #pragma unroll
            for (int p = 0; p < NP; p++) {
                float c = cent_s[tid*NP + p];
                s += c * c;
            }
            centn_s[tid] = s;
        }
    }
    __syncthreads();
    if (tid < NP) {
        float s = 0.f;
        #pragma unroll
        for (int w = 0; w < WARPS; w++) s += cpart[w*NP + tid];
        cvec[tid] = s;
    }
    __syncthreads();

    // ---- projection main loop: warp handles 4 tokens, f32x2 packed FMAs ----
    const int t0 = blockIdx.x * TPB + warp * TPW;
    const ulonglong2* xu0 = (const ulonglong2*)(x + (size_t)(t0 + 0) * HD);
    const ulonglong2* xu1 = (const ulonglong2*)(x + (size_t)(t0 + 1) * HD);
    const ulonglong2* xu2 = (const ulonglong2*)(x + (size_t)(t0 + 2) * HD);
    const ulonglong2* xu3 = (const ulonglong2*)(x + (size_t)(t0 + 3) * HD);
    const ulonglong2* cu  = (const ulonglong2*)comp_s;

    unsigned long long acc[TPW][NP];
    #pragma unroll
    for (int t = 0; t < TPW; t++)
        #pragma unroll
        for (int p = 0; p < NP; p++) acc[t][p] = 0ull;

    #pragma unroll 1
    for (int i = lane; i < HU; i += 32) {
        ulonglong2 xv0 = xu0[i];
        ulonglong2 xv1 = xu1[i];
        ulonglong2 xv2 = xu2[i];
        ulonglong2 xv3 = xu3[i];
        ulonglong2 c0 = cu[0*HU + i];
        ulonglong2 c1 = cu[1*HU + i];
        ulonglong2 c2 = cu[2*HU + i];
        ulonglong2 c3 = cu[3*HU + i];
        ulonglong2 c4 = cu[4*HU + i];
        ulonglong2 c5 = cu[5*HU + i];

        FMA2(acc[0][0], xv0.x, c0.x); FMA2(acc[0][0], xv0.y, c0.y);
        FMA2(acc[0][1], xv0.x, c1.x); FMA2(acc[0][1], xv0.y, c1.y);
        FMA2(acc[0][2], xv0.x, c2.x); FMA2(acc[0][2], xv0.y, c2.y);
        FMA2(acc[0][3], xv0.x, c3.x); FMA2(acc[0][3], xv0.y, c3.y);
        FMA2(acc[0][4], xv0.x, c4.x); FMA2(acc[0][4], xv0.y, c4.y);
        FMA2(acc[0][5], xv0.x, c5.x); FMA2(acc[0][5], xv0.y, c5.y);

        FMA2(acc[1][0], xv1.x, c0.x); FMA2(acc[1][0], xv1.y, c0.y);
        FMA2(acc[1][1], xv1.x, c1.x); FMA2(acc[1][1], xv1.y, c1.y);
        FMA2(acc[1][2], xv1.x, c2.x); FMA2(acc[1][2], xv1.y, c2.y);
        FMA2(acc[1][3], xv1.x, c3.x); FMA2(acc[1][3], xv1.y, c3.y);
        FMA2(acc[1][4], xv1.x, c4.x); FMA2(acc[1][4], xv1.y, c4.y);
        FMA2(acc[1][5], xv1.x, c5.x); FMA2(acc[1][5], xv1.y, c5.y);

        FMA2(acc[2][0], xv2.x, c0.x); FMA2(acc[2][0], xv2.y, c0.y);
        FMA2(acc[2][1], xv2.x, c1.x); FMA2(acc[2][1], xv2.y, c1.y);
        FMA2(acc[2][2], xv2.x, c2.x); FMA2(acc[2][2], xv2.y, c2.y);
        FMA2(acc[2][3], xv2.x, c3.x); FMA2(acc[2][3], xv2.y, c3.y);
        FMA2(acc[2][4], xv2.x, c4.x); FMA2(acc[2][4], xv2.y, c4.y);
        FMA2(acc[2][5], xv2.x, c5.x); FMA2(acc[2][5], xv2.y, c5.y);

        FMA2(acc[3][0], xv3.x, c0.x); FMA2(acc[3][0], xv3.y, c0.y);
        FMA2(acc[3][1], xv3.x, c1.x); FMA2(acc[3][1], xv3.y, c1.y);
        FMA2(acc[3][2], xv3.x, c2.x); FMA2(acc[3][2], xv3.y, c2.y);
        FMA2(acc[3][3], xv3.x, c3.x); FMA2(acc[3][3], xv3.y, c3.y);
        FMA2(acc[3][4], xv3.x, c4.x); FMA2(acc[3][4], xv3.y, c4.y);
        FMA2(acc[3][5], xv3.x, c5.x); FMA2(acc[3][5], xv3.y, c5.y);
    }

    // ---- reduce across warp, write proj (mean-corrected) to smem ----
    #pragma unroll
    for (int t = 0; t < TPW; t++) {
        #pragma unroll
        for (int p = 0; p < NP; p++) {
            unsigned long long v = acc[t][p];
            float s = __uint_as_float((unsigned)(v & 0xffffffffull)) +
                      __uint_as_float((unsigned)(v >> 32));
            #pragma unroll
            for (int o = 16; o > 0; o >>= 1)
                s += __shfl_xor_sync(0xffffffffu, s, o);
            if (lane == 0)
                proj_s[(warp*TPW + t)*NP + p] = s - cvec[p];
        }
    }
    __syncthreads();

    // ---- epilogue: distances, softmax over 64, top-8 ----
    float* out_idx = out;
    float* out_tp  = out + (size_t)NTOK * TK;
    float* out_pr  = out + 2 * (size_t)NTOK * TK;

    #pragma unroll 1
    for (int t = 0; t < TPW; t++) {
        const int tok = blockIdx.x * TPB + warp * TPW + t;
        float pr[NP];
        #pragma unroll
        for (int p = 0; p < NP; p++) pr[p] = proj_s[(warp*TPW + t)*NP + p];
        float pn = 0.f;
        #pragma unroll
        for (int p = 0; p < NP; p++) pn += pr[p] * pr[p];

        const int e0 = lane, e1 = lane + 32;
        float dot0 = 0.f, dot1 = 0.f;
        #pragma unroll
        for (int p = 0; p < NP; p++) {
            dot0 += pr[p] * cent_s[e0*NP + p];
            dot1 += pr[p] * cent_s[e1*NP + p];
        }
        float d20 = pn - 2.f*dot0 + centn_s[e0];
        float d21 = pn - 2.f*dot1 + centn_s[e1];
        float s0 = -sqrtf(fmaxf(d20, 0.f));
        float s1 = -sqrtf(fmaxf(d21, 0.f));

        // softmax over 64
        float m = fmaxf(s0, s1);
        #pragma unroll
        for (int o = 16; o > 0; o >>= 1)
            m = fmaxf(m, __shfl_xor_sync(0xffffffffu, m, o));
        float ex0 = expf(s0 - m);
        float ex1 = expf(s1 - m);
        float sum = ex0 + ex1;
        #pragma unroll
        for (int o = 16; o > 0; o >>= 1)
            sum += __shfl_xor_sync(0xffffffffu, sum, o);
        float p0 = ex0 / sum;
        float p1 = ex1 / sum;

        out_pr[(size_t)tok*NE + e0] = p0;
        out_pr[(size_t)tok*NE + e1] = p1;

        // top-8 via 8-round warp argmax; tie-break = lower index (jax.lax.top_k)
        unsigned long long k0 = ((unsigned long long)__float_as_uint(p0) << 32) | (unsigned)(NE-1 - e0);
        unsigned long long k1 = ((unsigned long long)__float_as_uint(p1) << 32) | (unsigned)(NE-1 - e1);
        float tsum = 0.f, myp = 0.f;
        int myi = 0;
        #pragma unroll
        for (int r = 0; r < TK; r++) {
            unsigned long long b = (k0 > k1) ? k0 : k1;
            #pragma unroll
            for (int o = 16; o > 0; o >>= 1) {
                unsigned long long v = __shfl_xor_sync(0xffffffffu, b, o);
                if (v > b) b = v;
            }
            int idx = NE-1 - (int)(b & 0xffull);
            float pv = __uint_as_float((unsigned)(b >> 32));
            tsum += pv;
            if (lane == r) { myp = pv; myi = idx; }
            if (idx == e0) k0 = 0ull;
            if (idx == e1) k1 = 0ull;
        }
        if (lane < TK) {
            out_idx[(size_t)tok*TK + lane] = (float)myi;
            out_tp [(size_t)tok*TK + lane] = myp / tsum;
        }
    }
}

extern "C" void kernel_launch(void* const* d_in, const int* in_sizes, int n_in,
                              void* d_out, int out_size)
{
    const float* x    = (const float*)d_in[0];
    const float* mean = (const float*)d_in[1];
    const float* comp = (const float*)d_in[2];
    const float* cent = (const float*)d_in[3];
    float* out = (float*)d_out;

    cudaFuncSetAttribute(kdtree_router_kernel,
                         cudaFuncAttributeMaxDynamicSharedMemorySize, SMEM_BYTES);
    kdtree_router_kernel<<<NTOK / TPB, NTHREADS, SMEM_BYTES>>>(x, mean, comp, cent, out);
}